// round 12
// baseline (speedup 1.0000x reference)
#include <cuda_runtime.h>
#include <cstdint>

// Problem constants (fixed by setup_inputs):
//   B=16, H_out=W_out=512 -> N = 262144 = 2^18
//   source: [B, 640, 640, 3] f32
//   idx:    [B, 2, N] f32
//   out:    [B, 512, 512, 3] f32
#define B_     16
#define N_     262144      // 2^18
#define N_LOG2 18
#define HS_    640
#define WS_    640
#define C_     3
#define PIX_PER_THREAD 4

// Predicated 16B read-only load, WRITE-ONLY destinations: predicated-off lanes
// leave garbage in the regs. Safe here because every garbage-reading slot is
// either discarded by a SEL (bitwise, NaN-safe) or overridden by the !valid
// zeroing below. Avoids ~18 dead MOV-0 per thread vs "+f" constraints.
__device__ __forceinline__ void ldg128_pred(float4& q, const float4* p, int pred)
{
    asm("{\n\t"
        ".reg .pred %%pq;\n\t"
        "setp.ne.b32 %%pq, %4, 0;\n\t"
        "@%%pq ld.global.nc.v4.f32 {%0,%1,%2,%3}, [%5];\n\t"
        "}"
        : "=f"(q.x), "=f"(q.y), "=f"(q.z), "=f"(q.w)
        : "r"(pred), "l"(p));
}

__device__ __forceinline__ void ldg64_pred(float2& q, const float2* p, int pred)
{
    asm("{\n\t"
        ".reg .pred %%pq;\n\t"
        "setp.ne.b32 %%pq, %2, 0;\n\t"
        "@%%pq ld.global.nc.v2.f32 {%0,%1}, [%3];\n\t"
        "}"
        : "=f"(q.x), "=f"(q.y)
        : "r"(pred), "l"(p));
}

// min-blocks 8 caps regs at 32: the live set provably fits (R5 compiled to 31
// regs with a superset of these instructions), so this reclaims 82% occupancy
// while keeping the dead-MOV elimination.
__global__ __launch_bounds__(256, 8)
void nn_gather_kernel(const float* __restrict__ idx,
                      const float* __restrict__ src,
                      float* __restrict__ out)
{
    const int64_t tid = (int64_t)blockIdx.x * blockDim.x + threadIdx.x;
    const int64_t p0  = tid * PIX_PER_THREAD;          // global pixel index
    const int     b   = (int)(p0 >> N_LOG2);
    const int     n   = (int)(p0 & (N_ - 1));          // multiple of 4 -> 16B aligned

    const float* idx_b = idx + (int64_t)b * 2 * N_;
    const float4 rv = *reinterpret_cast<const float4*>(idx_b + n);        // rows
    const float4 cv = *reinterpret_cast<const float4*>(idx_b + N_ + n);   // cols

    // per-image base, 16B aligned (1228800 floats per image)
    const float4* src4 = reinterpret_cast<const float4*>(src + (int64_t)b * (HS_ * WS_ * C_));

    const float rr[4] = {rv.x, rv.y, rv.z, rv.w};
    const float cc[4] = {cv.x, cv.y, cv.z, cv.w};

    // ---- phase 1: addresses + predicates for all 4 pixels ----
    int base4[4], rem[4], pv[4], pv2[4];
    #pragma unroll
    for (int k = 0; k < 4; ++k) {
        // trunc(x + 0.5) toward zero == __float2int_rz(x + 0.5f)
        const int ir = __float2int_rz(rr[k] + 0.5f);
        const int ic = __float2int_rz(cc[k] + 0.5f);
        const int valid = ((unsigned)ir < (unsigned)HS_) &
                          ((unsigned)ic < (unsigned)WS_);
        // clamp keeps the (dead) predicated-off address in-range
        const int irc = min(max(ir, 0), HS_ - 1);
        const int icc = min(max(ic, 0), WS_ - 1);
        const int off = (irc * WS_ + icc) * C_;   // float offset, 4B-aligned
        base4[k] = off >> 2;
        rem[k]   = off & 3;
        pv[k]    = valid;
        pv2[k]   = valid & (rem[k] >= 2);   // straddles 16B boundary
    }

    // ---- phase 2: all 8 predicated loads back-to-back (MLP ~8) ----
    float4 q0[4];
    float2 q1[4];
    #pragma unroll
    for (int k = 0; k < 4; ++k)
        ldg128_pred(q0[k], src4 + base4[k], pv[k]);
    #pragma unroll
    for (int k = 0; k < 4; ++k)
        ldg64_pred(q1[k], reinterpret_cast<const float2*>(src4 + base4[k] + 1), pv2[k]);

    // ---- phase 3: channel selects ----
    // Garbage-safety: for pv=0 all three slots are overridden to 0 below.
    // For pv=1 and rem<2, q1 is garbage but every select that could pick it
    // takes the q0 arm (e0|e1 true). Selects are bitwise -> NaN-safe.
    float o[12];
    #pragma unroll
    for (int k = 0; k < 4; ++k) {
        const bool e0 = (rem[k] == 0), e1 = (rem[k] == 1), e2 = (rem[k] == 2);
        o[3*k + 0] = e0 ? q0[k].x : e1 ? q0[k].y : e2 ? q0[k].z : q0[k].w;
        o[3*k + 1] = e0 ? q0[k].y : e1 ? q0[k].z : e2 ? q0[k].w : q1[k].x;
        o[3*k + 2] = e0 ? q0[k].z : e1 ? q0[k].w : e2 ? q1[k].x : q1[k].y;
        if (!pv[k]) { o[3*k+0] = 0.f; o[3*k+1] = 0.f; o[3*k+2] = 0.f; }
    }

    // 4 pixels * 3ch = 12 floats = 48B at byte offset 48*tid -> 16B aligned
    float4* op = reinterpret_cast<float4*>(out + p0 * C_);
    op[0] = make_float4(o[0], o[1],  o[2],  o[3]);
    op[1] = make_float4(o[4], o[5],  o[6],  o[7]);
    op[2] = make_float4(o[8], o[9],  o[10], o[11]);
}

extern "C" void kernel_launch(void* const* d_in, const int* in_sizes, int n_in,
                              void* d_out, int out_size)
{
    const float* idx = (const float*)d_in[0];   // [B, 2, N] f32
    const float* src = (const float*)d_in[1];   // [B, 640, 640, 3] f32
    float* out = (float*)d_out;                 // [B, 512, 512, 3] f32

    const int64_t total_pixels  = (int64_t)B_ * N_;                 // 4,194,304
    const int64_t total_threads = total_pixels / PIX_PER_THREAD;    // 1,048,576
    const int threads = 256;
    const int blocks  = (int)(total_threads / threads);             // 4096

    nn_gather_kernel<<<blocks, threads>>>(idx, src, out);
}

// round 13
// speedup vs baseline: 1.2811x; 1.2811x over previous
#include <cuda_runtime.h>
#include <cstdint>

// Problem constants (fixed by setup_inputs):
//   B=16, H_out=W_out=512 -> N = 262144 = 2^18
//   source: [B, 640, 640, 3] f32  (1228800 floats = 153600 32B-units per image)
//   idx:    [B, 2, N] f32
//   out:    [B, 512, 512, 3] f32
#define B_     16
#define N_     262144      // 2^18
#define N_LOG2 18
#define HS_    640
#define WS_    640
#define C_     3
#define PIX_PER_THREAD 4

struct f8 { float a0,a1,a2,a3,a4,a5,a6,a7; };

// Predicated 32B (256-bit, sm_100+) read-only load, write-only destinations.
// Off-lanes produce no transaction and leave garbage (discarded downstream).
__device__ __forceinline__ void ldg256_pred(f8& q, const float* p, int pred)
{
    asm("{\n\t"
        ".reg .pred %%pq;\n\t"
        "setp.ne.b32 %%pq, %8, 0;\n\t"
        "@%%pq ld.global.nc.v8.f32 {%0,%1,%2,%3,%4,%5,%6,%7}, [%9];\n\t"
        "}"
        : "=f"(q.a0), "=f"(q.a1), "=f"(q.a2), "=f"(q.a3),
          "=f"(q.a4), "=f"(q.a5), "=f"(q.a6), "=f"(q.a7)
        : "r"(pred), "l"(p));
}

__device__ __forceinline__ void ldg64_pred(float2& q, const float* p, int pred)
{
    asm("{\n\t"
        ".reg .pred %%pq;\n\t"
        "setp.ne.b32 %%pq, %2, 0;\n\t"
        "@%%pq ld.global.nc.v2.f32 {%0,%1}, [%3];\n\t"
        "}"
        : "=f"(q.x), "=f"(q.y)
        : "r"(pred), "l"(p));
}

// NOTE: no min-blocks clause — R12 proved capping registers serializes the
// batched loads (MLP collapse). Free allocation @ ~50% occ is the fast point.
__global__ __launch_bounds__(256)
void nn_gather_kernel(const float* __restrict__ idx,
                      const float* __restrict__ src,
                      float* __restrict__ out)
{
    const int64_t tid = (int64_t)blockIdx.x * blockDim.x + threadIdx.x;
    const int64_t p0  = tid * PIX_PER_THREAD;          // global pixel index
    const int     b   = (int)(p0 >> N_LOG2);
    const int     n   = (int)(p0 & (N_ - 1));          // multiple of 4 -> 16B aligned

    const float* idx_b = idx + (int64_t)b * 2 * N_;
    const float4 rv = *reinterpret_cast<const float4*>(idx_b + n);        // rows
    const float4 cv = *reinterpret_cast<const float4*>(idx_b + N_ + n);   // cols

    const float* src_b = src + (int64_t)b * (HS_ * WS_ * C_);   // 32B aligned

    const float rr[4] = {rv.x, rv.y, rv.z, rv.w};
    const float cc[4] = {cv.x, cv.y, cv.z, cv.w};

    // ---- phase 1: addresses + predicates for all 4 pixels ----
    // 32B units: straddle only when (off & 7) >= 6  -> 25% of pixels
    // (vs 50% with 16B units) => gather wavefronts 1.5 -> 1.25 per pixel.
    int base8[4], rem[4], pv[4], pv2[4];
    #pragma unroll
    for (int k = 0; k < 4; ++k) {
        // trunc(x + 0.5) toward zero == __float2int_rz(x + 0.5f)
        const int ir = __float2int_rz(rr[k] + 0.5f);
        const int ic = __float2int_rz(cc[k] + 0.5f);
        const int valid = ((unsigned)ir < (unsigned)HS_) &
                          ((unsigned)ic < (unsigned)WS_);
        // clamp keeps the (dead) predicated-off address in-range
        const int irc = min(max(ir, 0), HS_ - 1);
        const int icc = min(max(ic, 0), WS_ - 1);
        const int off = (irc * WS_ + icc) * C_;   // float offset, multiple of 3
        base8[k] = off >> 3;                      // 32B unit index
        rem[k]   = off & 7;                       // 0..7
        pv[k]    = valid;
        pv2[k]   = valid & (rem[k] >= 6);         // straddles 32B boundary
    }

    // ---- phase 2: 4 v8 + (avg 1) predicated v2 loads, front-batched ----
    f8     q0[4];
    float2 q1[4];
    #pragma unroll
    for (int k = 0; k < 4; ++k)
        ldg256_pred(q0[k], src_b + ((int64_t)base8[k] << 3), pv[k]);
    #pragma unroll
    for (int k = 0; k < 4; ++k)
        ldg64_pred(q1[k], src_b + (((int64_t)base8[k] + 1) << 3), pv2[k]);

    // ---- phase 3: 8-way channel selects (SEL trees, NaN/garbage-safe) ----
    float o[12];
    #pragma unroll
    for (int k = 0; k < 4; ++k) {
        const int r = rem[k];
        const f8&    q = q0[k];
        const float2 x = q1[k];
        // channel c lives at float index r + c within [q.a0..q.a7, x.x, x.y]
        const float v0 =
            r==0 ? q.a0 : r==1 ? q.a1 : r==2 ? q.a2 : r==3 ? q.a3 :
            r==4 ? q.a4 : r==5 ? q.a5 : r==6 ? q.a6 :          q.a7;
        const float v1 =
            r==0 ? q.a1 : r==1 ? q.a2 : r==2 ? q.a3 : r==3 ? q.a4 :
            r==4 ? q.a5 : r==5 ? q.a6 : r==6 ? q.a7 :          x.x;
        const float v2 =
            r==0 ? q.a2 : r==1 ? q.a3 : r==2 ? q.a4 : r==3 ? q.a5 :
            r==4 ? q.a6 : r==5 ? q.a7 : r==6 ? x.x  :          x.y;
        // invalid pixels: loads were predicated off (garbage) -> force zeros
        o[3*k + 0] = pv[k] ? v0 : 0.0f;
        o[3*k + 1] = pv[k] ? v1 : 0.0f;
        o[3*k + 2] = pv[k] ? v2 : 0.0f;
    }

    // 4 pixels * 3ch = 12 floats = 48B at byte offset 48*tid -> 16B aligned
    float4* op = reinterpret_cast<float4*>(out + p0 * C_);
    op[0] = make_float4(o[0], o[1],  o[2],  o[3]);
    op[1] = make_float4(o[4], o[5],  o[6],  o[7]);
    op[2] = make_float4(o[8], o[9],  o[10], o[11]);
}

extern "C" void kernel_launch(void* const* d_in, const int* in_sizes, int n_in,
                              void* d_out, int out_size)
{
    const float* idx = (const float*)d_in[0];   // [B, 2, N] f32
    const float* src = (const float*)d_in[1];   // [B, 640, 640, 3] f32
    float* out = (float*)d_out;                 // [B, 512, 512, 3] f32

    const int64_t total_pixels  = (int64_t)B_ * N_;                 // 4,194,304
    const int64_t total_threads = total_pixels / PIX_PER_THREAD;    // 1,048,576
    const int threads = 256;
    const int blocks  = (int)(total_threads / threads);             // 4096

    nn_gather_kernel<<<blocks, threads>>>(idx, src, out);
}